// round 7
// baseline (speedup 1.0000x reference)
#include <cuda_runtime.h>
#include <cstdint>
#include <cstddef>

// Problem constants
#define B_   256
#define S_   256
#define D_   1024
#define P_   512
#define SH   254
#define NROWS (B_*SH)       // 65024
#define EPS_ 1e-7f

// Scratch (__device__ globals: allocation-free rule)
__device__ float g_bias[B_*P_];
__device__ float g_spart[2*NROWS];                    // per-N-block score partials
__device__ int   g_mask_mode;
__device__ __align__(1024) float g_w1t[(size_t)P_*D_];   // proj_head^T [512][1024] (tf32-rounded)
__device__ __align__(1024) float g_h0t[(size_t)P_*P_];   // hidden0^T  [512][512]
__device__ __align__(1024) float g_h1t[(size_t)P_*P_];   // hidden1^T  [512][512]
__device__ __align__(1024) float g_c0[(size_t)NROWS*P_]; // activations after stage 1 (tf32-rounded)
__device__ __align__(1024) float g_c1[(size_t)NROWS*P_]; // activations after stage 2 (tf32-rounded)

__device__ __forceinline__ float fast_tanh(float x) {
    float y; asm("tanh.approx.f32 %0, %1;" : "=f"(y) : "f"(x)); return y;
}
__device__ __forceinline__ uint32_t smem_u32(const void* p) {
    uint32_t a;
    asm("{ .reg .u64 t; cvta.to.shared.u64 t, %1; cvt.u32.u64 %0, t; }" : "=r"(a) : "l"(p));
    return a;
}
__device__ __forceinline__ uint32_t tf32_rna(uint32_t u) {
    uint32_t r; float f = __uint_as_float(u);
    asm("cvt.rna.tf32.f32 %0, %1;" : "=r"(r) : "f"(f));
    return r;
}
__device__ __forceinline__ float tf32_rna_f(float f) {
    float r; asm("cvt.rna.tf32.f32 %0, %1;" : "=f"(r) : "f"(f)); return r;
}

// ---------------------------------------------------------------------------
// mask dtype probe (reads only first 65536 bytes; deterministic)
// ---------------------------------------------------------------------------
__global__ void __launch_bounds__(256) mask_probe_kernel(const unsigned int* __restrict__ m)
{
    __shared__ int s01, sf;
    if (threadIdx.x == 0) { s01 = 1; sf = 1; }
    __syncthreads();
    bool ok01 = true, okf = true;
    #pragma unroll 4
    for (int it = 0; it < 64; it++) {
        unsigned int v = m[threadIdx.x + it * 256];
        if (v > 1u) ok01 = false;
        if (v != 0u && v != 0x3F800000u) okf = false;
    }
    if (!ok01) atomicAnd(&s01, 0);
    if (!okf)  atomicAnd(&sf, 0);
    __syncthreads();
    if (threadIdx.x == 0) g_mask_mode = s01 ? 0 : (sf ? 1 : 2);
}

// ---------------------------------------------------------------------------
// One launch: transpose all 3 weight matrices W[K][N] -> Wt[N][K], tf32-rna.
// ---------------------------------------------------------------------------
__global__ void __launch_bounds__(256) transpose_all(
    const float* __restrict__ w_head, const float* __restrict__ hid)
{
    const int z = blockIdx.z;
    const int K = (z == 0) ? D_ : P_;
    if (blockIdx.y * 32 >= K) return;
    const float* src = (z == 0) ? w_head : (hid + (size_t)(z - 1) * P_ * P_);
    float* dst = (z == 0) ? g_w1t : ((z == 1) ? g_h0t : g_h1t);

    __shared__ float t[32][33];
    int k0 = blockIdx.y * 32, n0 = blockIdx.x * 32;
    int tx = threadIdx.x & 31, ty = threadIdx.x >> 5;   // 32 x 8
    #pragma unroll
    for (int i = 0; i < 32; i += 8)
        t[ty + i][tx] = src[(size_t)(k0 + ty + i) * P_ + n0 + tx];
    __syncthreads();
    #pragma unroll
    for (int i = 0; i < 32; i += 8)
        dst[(size_t)(n0 + ty + i) * K + k0 + tx] = tf32_rna_f(t[tx][ty + i]);
}

// ---------------------------------------------------------------------------
// bias kernel: bias[b][p] = prep·proj_prep[:,p] + child·proj_child[:,p] (fp32)
// ---------------------------------------------------------------------------
__global__ void __launch_bounds__(128) bias_kernel(
    const float* __restrict__ x,
    const float* __restrict__ wp,
    const float* __restrict__ wc)
{
    __shared__ float sP[4][D_];
    __shared__ float sC[4][D_];
    const int tid = threadIdx.x;
    const int b0  = blockIdx.y * 4;
    #pragma unroll
    for (int it = 0; it < 16; it++) {
        int idx  = tid + it * 128;
        int row  = idx >> 8;
        int col4 = idx & 255;
        int bb   = b0 + (row >> 1);
        int which = row & 1;
        const float* src = x + ((size_t)bb * S_ + (S_ - 2) + which) * D_;
        float4 v = *(const float4*)(src + col4 * 4);
        float* dst = which ? &sC[row >> 1][0] : &sP[row >> 1][0];
        *(float4*)(dst + col4 * 4) = v;
    }
    __syncthreads();
    const int p = blockIdx.x * 128 + tid;
    float acc[4] = {0.f, 0.f, 0.f, 0.f};
    #pragma unroll 4
    for (int d = 0; d < D_; d++) {
        float a = wp[(size_t)d * P_ + p];
        float c = wc[(size_t)d * P_ + p];
        #pragma unroll
        for (int j = 0; j < 4; j++) acc[j] += sP[j][d] * a + sC[j][d] * c;
    }
    #pragma unroll
    for (int j = 0; j < 4; j++)
        g_bias[(size_t)(b0 + j) * P_ + p] = acc[j];
}

// ---------------------------------------------------------------------------
// tf32 mma.sync GEMM stage. CTA tile 128x256, BK=32, 3-stage cp.async pipeline.
// 8 warps = 2M x 4N, warp tile 64x64 (halves LDSM + addr work per MMA vs 64x32).
// 1 CTA/SM (regs ~190, smem 144KB). grid = (2 N-blocks, 508 row-blocks).
// EPI: 0 = +bias,tanh,rna -> Cout ; 1 = tanh,rna -> Cout ; 2 = tanh + scorer partial
// smem per stage (49152 B): A[128][32] @0, B[256][32] @16384. 128B rows, XOR swizzle.
// ---------------------------------------------------------------------------
#define GSMEM 147456

template<int K, int EPI>
__global__ void __launch_bounds__(256) gemm_tf32(
    const float* __restrict__ A,
    const float* __restrict__ BT,
    const float* __restrict__ scorer,
    float* __restrict__ Cout)
{
    constexpr int T = K / 32;
    extern __shared__ __align__(1024) char smem[];
    const uint32_t sb = smem_u32(smem);
    const int tid = threadIdx.x, lane = tid & 31, wid = tid >> 5;
    const int wm = wid >> 2, wn = wid & 3;
    const int N0 = blockIdx.x * 256, R0 = blockIdx.y * 128;

    // ---- cp.async offsets. chunk c = tid&7 (16B within 128B row), base row tid>>3.
    // A: rows r0+32i (i<4); B: rows r0+32i (i<8). Swizzle constant across i (32 ≡ 0 mod 8).
    const int r0 = tid >> 3, cc = tid & 7;
    const uint32_t sA0 = (uint32_t)(r0 * 128 + ((cc ^ (r0 & 7)) << 4));
    uint32_t aoff[4];
    #pragma unroll
    for (int i = 0; i < 4; i++) {
        int r = R0 + r0 + i * 32;
        if (EPI == 0) {
            int b = r / SH; int s2 = r - b * SH;
            aoff[i] = (uint32_t)(((b * S_ + s2) * D_ + cc * 4) * 4);
        } else {
            aoff[i] = (uint32_t)((r * K + cc * 4) * 4);
        }
    }
    const uint32_t boff0 = (uint32_t)(((N0 + r0) * K + cc * 4) * 4);
    const char* Ab = (const char*)A;
    const char* Bb = (const char*)BT;

    auto fill = [&](int slot, int kt) {
        uint32_t base = sb + slot * 49152;
        uint32_t koff = (uint32_t)kt * 128;
        #pragma unroll
        for (int i = 0; i < 4; i++)
            asm volatile("cp.async.cg.shared.global [%0], [%1], 16;"
                :: "r"(base + sA0 + i * 4096), "l"(Ab + aoff[i] + koff) : "memory");
        #pragma unroll
        for (int i = 0; i < 8; i++)
            asm volatile("cp.async.cg.shared.global [%0], [%1], 16;"
                :: "r"(base + 16384 + sA0 + i * 4096),
                   "l"(Bb + boff0 + (uint32_t)i * (128u * K) + koff) : "memory");
        asm volatile("cp.async.commit_group;" ::: "memory");
    };

    float acc[4][8][4];
    #pragma unroll
    for (int a = 0; a < 4; a++)
        #pragma unroll
        for (int b = 0; b < 8; b++)
            #pragma unroll
            for (int c = 0; c < 4; c++) acc[a][b][c] = 0.f;

    fill(0, 0);
    fill(1, 1);
    fill(2, 2);

    // ldmatrix per-thread invariants
    const int aswz = lane & 7;
    const int arow = (lane & 7) + ((lane >> 3) & 1) * 8;
    const int ach  = (lane >> 4) & 1;
    const int brow = (lane & 7) + ((lane >> 4) & 1) * 8;
    const int bch  = (lane >> 3) & 1;

    for (int t = 0; t < T; t++) {
        int rem = T - 1 - t;
        if (rem >= 2)      asm volatile("cp.async.wait_group 2;" ::: "memory");
        else if (rem == 1) asm volatile("cp.async.wait_group 1;" ::: "memory");
        else               asm volatile("cp.async.wait_group 0;" ::: "memory");
        __syncthreads();

        const int slot = t % 3;
        const uint32_t ab = sb + slot * 49152;
        const uint32_t bbs = ab + 16384;
        #pragma unroll
        for (int kk = 0; kk < 4; kk++) {
            uint32_t ar[4][4], br[4][4];
            #pragma unroll
            for (int mi = 0; mi < 4; mi++) {
                uint32_t addr = ab + (uint32_t)((wm * 64 + mi * 16 + arow) * 128)
                              + (uint32_t)((((kk * 2 + ach) ^ aswz)) << 4);
                asm volatile("ldmatrix.sync.aligned.m8n8.x4.shared.b16 {%0,%1,%2,%3}, [%4];"
                    : "=r"(ar[mi][0]), "=r"(ar[mi][1]), "=r"(ar[mi][2]), "=r"(ar[mi][3])
                    : "r"(addr));
            }
            #pragma unroll
            for (int np = 0; np < 4; np++) {
                uint32_t addr = bbs + (uint32_t)((wn * 64 + np * 16 + brow) * 128)
                              + (uint32_t)((((kk * 2 + bch) ^ aswz)) << 4);
                asm volatile("ldmatrix.sync.aligned.m8n8.x4.shared.b16 {%0,%1,%2,%3}, [%4];"
                    : "=r"(br[np][0]), "=r"(br[np][1]), "=r"(br[np][2]), "=r"(br[np][3])
                    : "r"(addr));
            }
            if (EPI == 0) {
                #pragma unroll
                for (int mi = 0; mi < 4; mi++)
                    #pragma unroll
                    for (int j = 0; j < 4; j++) ar[mi][j] = tf32_rna(ar[mi][j]);
            }
            #pragma unroll
            for (int mi = 0; mi < 4; mi++)
                #pragma unroll
                for (int nj = 0; nj < 8; nj++) {
                    uint32_t b0 = br[nj >> 1][(nj & 1) * 2];
                    uint32_t b1 = br[nj >> 1][(nj & 1) * 2 + 1];
                    asm volatile(
                        "mma.sync.aligned.m16n8k8.row.col.f32.tf32.tf32.f32 "
                        "{%0,%1,%2,%3}, {%4,%5,%6,%7}, {%8,%9}, {%0,%1,%2,%3};"
                        : "+f"(acc[mi][nj][0]), "+f"(acc[mi][nj][1]),
                          "+f"(acc[mi][nj][2]), "+f"(acc[mi][nj][3])
                        : "r"(ar[mi][0]), "r"(ar[mi][1]), "r"(ar[mi][2]), "r"(ar[mi][3]),
                          "r"(b0), "r"(b1));
                }
        }
        __syncthreads();
        if (t + 3 < T) fill(slot, t + 3);
    }

    // ---- epilogue ----
    const int r4 = lane >> 2, l2 = (lane & 3) * 2;
    if (EPI < 2) {
        #pragma unroll
        for (int mi = 0; mi < 4; mi++)
            #pragma unroll
            for (int h = 0; h < 2; h++) {
                int m = R0 + wm * 64 + mi * 16 + r4 + h * 8;
                const float* brow_ = g_bias + (size_t)(m / SH) * P_;
                #pragma unroll
                for (int nj = 0; nj < 8; nj++) {
                    int n = N0 + wn * 64 + nj * 8 + l2;
                    float v0 = acc[mi][nj][h * 2 + 0];
                    float v1 = acc[mi][nj][h * 2 + 1];
                    if (EPI == 0) {
                        float2 bv = *(const float2*)(brow_ + n);
                        v0 += bv.x; v1 += bv.y;
                    }
                    float2 o;
                    o.x = tf32_rna_f(fast_tanh(v0));
                    o.y = tf32_rna_f(fast_tanh(v1));
                    *(float2*)(Cout + (size_t)m * P_ + n) = o;
                }
            }
    } else {
        __syncthreads();                    // smem reuse for reduction
        float* red = (float*)smem;          // [4][128]
        #pragma unroll
        for (int mi = 0; mi < 4; mi++)
            #pragma unroll
            for (int h = 0; h < 2; h++) {
                float sum = 0.f;
                #pragma unroll
                for (int nj = 0; nj < 8; nj++) {
                    int n = N0 + wn * 64 + nj * 8 + l2;
                    float v0 = fast_tanh(acc[mi][nj][h * 2 + 0]);
                    float v1 = fast_tanh(acc[mi][nj][h * 2 + 1]);
                    sum += v0 * __ldg(scorer + n) + v1 * __ldg(scorer + n + 1);
                }
                sum += __shfl_xor_sync(0xffffffffu, sum, 1);
                sum += __shfl_xor_sync(0xffffffffu, sum, 2);
                if ((lane & 3) == 0)
                    red[wn * 128 + wm * 64 + mi * 16 + r4 + h * 8] = sum;
            }
        __syncthreads();
        if (tid < 128) {
            float tot = red[tid] + red[128 + tid] + red[256 + tid] + red[384 + tid];
            g_spart[(size_t)blockIdx.x * NROWS + R0 + tid] = tot;
        }
    }
}

// ---------------------------------------------------------------------------
// masked softmax over s per batch; sums the 2 N-block score partials.
// ---------------------------------------------------------------------------
__global__ void __launch_bounds__(256) softmax_kernel(
    const void* __restrict__ mask_raw, float* __restrict__ out)
{
    __shared__ float red[256];
    const int b = blockIdx.x;
    const int s = threadIdx.x;
    const int mode = g_mask_mode;
    float e = 0.f;
    if (s < SH) {
        bool m;
        int idx = b * S_ + s;
        if (mode == 0)      m = ((const int*)mask_raw)[idx] != 0;
        else if (mode == 1) m = ((const float*)mask_raw)[idx] != 0.f;
        else                m = ((const unsigned char*)mask_raw)[idx] != 0;
        int r = b * SH + s;
        float sc = g_spart[r] + g_spart[NROWS + r];
        e = m ? expf(sc) : 0.f;
    }
    red[s] = e;
    __syncthreads();
    #pragma unroll
    for (int o = 128; o > 0; o >>= 1) {
        if (s < o) red[s] += red[s + o];
        __syncthreads();
    }
    float inv = 1.f / (red[0] + EPS_);
    if (s < SH) out[b * SH + s] = e * inv;
}

// ---------------------------------------------------------------------------
extern "C" void kernel_launch(void* const* d_in, const int* in_sizes, int n_in,
                              void* d_out, int out_size)
{
    // Resolve inputs by element count (robust to metadata ordering).
    int xi = -1, si = -1, mi = -1;
    int q[4] = {-1, -1, -1, -1};
    int nq = 0;
    for (int i = 0; i < n_in; i++) {
        long long sz = in_sizes[i];
        if (sz == (long long)B_ * S_ * D_)      xi = i;
        else if (sz == P_)                      si = i;
        else if (sz == (long long)B_ * S_)      mi = i;
        else if (sz == (long long)D_ * P_ && nq < 4) q[nq++] = i;
    }
    if (xi < 0 || si < 0 || mi < 0 || nq != 4) {
        xi = 0; q[0] = 1; q[1] = 2; q[2] = 3; q[3] = 4; si = 5; mi = 6;
    }
    const float *w_head, *w_prep, *w_child, *hid;
    if (xi == 0) {
        w_head = (const float*)d_in[q[0]];
        w_prep = (const float*)d_in[q[1]];
        w_child = (const float*)d_in[q[2]];
        hid    = (const float*)d_in[q[3]];
    } else {
        hid    = (const float*)d_in[q[0]];
        w_child = (const float*)d_in[q[1]];
        w_head = (const float*)d_in[q[2]];
        w_prep = (const float*)d_in[q[3]];
    }
    const float* x = (const float*)d_in[xi];
    const float* scorer = (const float*)d_in[si];
    const void* mask = d_in[mi];
    float* out = (float*)d_out;

    float *w1t_p, *h0t_p, *h1t_p, *c0_p, *c1_p;
    cudaGetSymbolAddress((void**)&w1t_p, g_w1t);
    cudaGetSymbolAddress((void**)&h0t_p, g_h0t);
    cudaGetSymbolAddress((void**)&h1t_p, g_h1t);
    cudaGetSymbolAddress((void**)&c0_p,  g_c0);
    cudaGetSymbolAddress((void**)&c1_p,  g_c1);

    cudaFuncSetAttribute(gemm_tf32<1024,0>, cudaFuncAttributeMaxDynamicSharedMemorySize, GSMEM);
    cudaFuncSetAttribute(gemm_tf32<512,1>,  cudaFuncAttributeMaxDynamicSharedMemorySize, GSMEM);
    cudaFuncSetAttribute(gemm_tf32<512,2>,  cudaFuncAttributeMaxDynamicSharedMemorySize, GSMEM);

    mask_probe_kernel<<<1, 256>>>((const unsigned int*)mask);
    transpose_all<<<dim3(P_/32, D_/32, 3), 256>>>(w_head, hid);
    bias_kernel<<<dim3(P_/128, B_/4), 128>>>(x, w_prep, w_child);

    gemm_tf32<1024,0><<<dim3(2, NROWS/128), 256, GSMEM>>>(x,    w1t_p, scorer, c0_p);
    gemm_tf32<512,1> <<<dim3(2, NROWS/128), 256, GSMEM>>>(c0_p, h0t_p, scorer, c1_p);
    gemm_tf32<512,2> <<<dim3(2, NROWS/128), 256, GSMEM>>>(c1_p, h1t_p, scorer, nullptr);

    softmax_kernel<<<B_, 256>>>(mask, out);
}

// round 9
// speedup vs baseline: 1.1417x; 1.1417x over previous
#include <cuda_runtime.h>
#include <cstdint>
#include <cstddef>

// Problem constants
#define B_   256
#define S_   256
#define D_   1024
#define P_   512
#define SH   254
#define NROWS (B_*SH)       // 65024
#define EPS_ 1e-7f

// Scratch (__device__ globals: allocation-free rule)
__device__ float g_bias[B_*P_];
__device__ float g_spart[4*NROWS];                    // per-N-block score partials
__device__ int   g_mask_mode;
__device__ __align__(1024) float g_w1t[(size_t)P_*D_];   // proj_head^T [512][1024] (tf32-rounded)
__device__ __align__(1024) float g_h0t[(size_t)P_*P_];   // hidden0^T  [512][512]
__device__ __align__(1024) float g_h1t[(size_t)P_*P_];   // hidden1^T  [512][512]
__device__ __align__(1024) float g_c0[(size_t)NROWS*P_]; // activations after stage 1 (tf32-rounded)
__device__ __align__(1024) float g_c1[(size_t)NROWS*P_]; // activations after stage 2 (tf32-rounded)

__device__ __forceinline__ float fast_tanh(float x) {
    float y; asm("tanh.approx.f32 %0, %1;" : "=f"(y) : "f"(x)); return y;
}
__device__ __forceinline__ uint32_t smem_u32(const void* p) {
    uint32_t a;
    asm("{ .reg .u64 t; cvta.to.shared.u64 t, %1; cvt.u32.u64 %0, t; }" : "=r"(a) : "l"(p));
    return a;
}
__device__ __forceinline__ uint32_t tf32_rna(uint32_t u) {
    uint32_t r; float f = __uint_as_float(u);
    asm("cvt.rna.tf32.f32 %0, %1;" : "=r"(r) : "f"(f));
    return r;
}
__device__ __forceinline__ float tf32_rna_f(float f) {
    float r; asm("cvt.rna.tf32.f32 %0, %1;" : "=f"(r) : "f"(f)); return r;
}

// ---------------------------------------------------------------------------
// mask dtype probe (reads only first 65536 bytes; deterministic)
// ---------------------------------------------------------------------------
__global__ void __launch_bounds__(256) mask_probe_kernel(const unsigned int* __restrict__ m)
{
    __shared__ int s01, sf;
    if (threadIdx.x == 0) { s01 = 1; sf = 1; }
    __syncthreads();
    bool ok01 = true, okf = true;
    #pragma unroll 4
    for (int it = 0; it < 64; it++) {
        unsigned int v = m[threadIdx.x + it * 256];
        if (v > 1u) ok01 = false;
        if (v != 0u && v != 0x3F800000u) okf = false;
    }
    if (!ok01) atomicAnd(&s01, 0);
    if (!okf)  atomicAnd(&sf, 0);
    __syncthreads();
    if (threadIdx.x == 0) g_mask_mode = s01 ? 0 : (sf ? 1 : 2);
}

// ---------------------------------------------------------------------------
// One launch: transpose all 3 weight matrices W[K][N] -> Wt[N][K], tf32-rna.
// ---------------------------------------------------------------------------
__global__ void __launch_bounds__(256) transpose_all(
    const float* __restrict__ w_head, const float* __restrict__ hid)
{
    const int z = blockIdx.z;
    const int K = (z == 0) ? D_ : P_;
    if (blockIdx.y * 32 >= K) return;
    const float* src = (z == 0) ? w_head : (hid + (size_t)(z - 1) * P_ * P_);
    float* dst = (z == 0) ? g_w1t : ((z == 1) ? g_h0t : g_h1t);

    __shared__ float t[32][33];
    int k0 = blockIdx.y * 32, n0 = blockIdx.x * 32;
    int tx = threadIdx.x & 31, ty = threadIdx.x >> 5;   // 32 x 8
    #pragma unroll
    for (int i = 0; i < 32; i += 8)
        t[ty + i][tx] = src[(size_t)(k0 + ty + i) * P_ + n0 + tx];
    __syncthreads();
    #pragma unroll
    for (int i = 0; i < 32; i += 8)
        dst[(size_t)(n0 + ty + i) * K + k0 + tx] = tf32_rna_f(t[tx][ty + i]);
}

// ---------------------------------------------------------------------------
// bias kernel: bias[b][p] = prep·proj_prep[:,p] + child·proj_child[:,p] (fp32)
// ---------------------------------------------------------------------------
__global__ void __launch_bounds__(128) bias_kernel(
    const float* __restrict__ x,
    const float* __restrict__ wp,
    const float* __restrict__ wc)
{
    __shared__ float sP[4][D_];
    __shared__ float sC[4][D_];
    const int tid = threadIdx.x;
    const int b0  = blockIdx.y * 4;
    #pragma unroll
    for (int it = 0; it < 16; it++) {
        int idx  = tid + it * 128;
        int row  = idx >> 8;
        int col4 = idx & 255;
        int bb   = b0 + (row >> 1);
        int which = row & 1;
        const float* src = x + ((size_t)bb * S_ + (S_ - 2) + which) * D_;
        float4 v = *(const float4*)(src + col4 * 4);
        float* dst = which ? &sC[row >> 1][0] : &sP[row >> 1][0];
        *(float4*)(dst + col4 * 4) = v;
    }
    __syncthreads();
    const int p = blockIdx.x * 128 + tid;
    float acc[4] = {0.f, 0.f, 0.f, 0.f};
    #pragma unroll 4
    for (int d = 0; d < D_; d++) {
        float a = wp[(size_t)d * P_ + p];
        float c = wc[(size_t)d * P_ + p];
        #pragma unroll
        for (int j = 0; j < 4; j++) acc[j] += sP[j][d] * a + sC[j][d] * c;
    }
    #pragma unroll
    for (int j = 0; j < 4; j++)
        g_bias[(size_t)(b0 + j) * P_ + p] = acc[j];
}

// ---------------------------------------------------------------------------
// tf32 mma.sync GEMM stage. CTA = 128 threads (4 warps, 2M x 2N), tile 128x128,
// warp tile 64x64, BK=32, 3-stage cp.async pipeline, 96KB smem -> 2 CTAs/SM.
// Combines R7's low LDSM/MMA ratio (0.25) with R6's cross-CTA sync overlap.
// EPI: 0 = +bias,tanh,rna -> Cout ; 1 = tanh,rna -> Cout ; 2 = tanh + scorer partial
// smem per stage (32768 B): A[128][32] @0, B[128][32] @16384. 128B rows, XOR swizzle.
// ---------------------------------------------------------------------------
#define GSMEM 98304

template<int K, int EPI>
__global__ void __launch_bounds__(128, 2) gemm_tf32(
    const float* __restrict__ A,
    const float* __restrict__ BT,
    const float* __restrict__ scorer,
    float* __restrict__ Cout)
{
    constexpr int T = K / 32;
    extern __shared__ __align__(1024) char smem[];
    const uint32_t sb = smem_u32(smem);
    const int tid = threadIdx.x, lane = tid & 31, wid = tid >> 5;
    const int wm = wid >> 1, wn = wid & 1;
    const int N0 = blockIdx.x * 128, R0 = blockIdx.y * 128;

    // ---- cp.async offsets. 128 threads; chunk cc = tid&7, base row r0 = tid>>3.
    // A/B rows r0 + 16i (i<8); swizzle constant across i (16 ≡ 0 mod 8).
    const int r0 = tid >> 3, cc = tid & 7;
    const uint32_t sA0 = (uint32_t)(r0 * 128 + ((cc ^ (r0 & 7)) << 4));
    uint32_t aoff[8];
    #pragma unroll
    for (int i = 0; i < 8; i++) {
        int r = R0 + r0 + i * 16;
        if (EPI == 0) {
            int b = r / SH; int s2 = r - b * SH;
            aoff[i] = (uint32_t)(((b * S_ + s2) * D_ + cc * 4) * 4);
        } else {
            aoff[i] = (uint32_t)((r * K + cc * 4) * 4);
        }
    }
    const uint32_t boff0 = (uint32_t)(((N0 + r0) * K + cc * 4) * 4);
    const char* Ab = (const char*)A;
    const char* Bb = (const char*)BT;

    auto fill = [&](int slot, int kt) {
        uint32_t base = sb + slot * 32768;
        uint32_t koff = (uint32_t)kt * 128;
        #pragma unroll
        for (int i = 0; i < 8; i++)
            asm volatile("cp.async.cg.shared.global [%0], [%1], 16;"
                :: "r"(base + sA0 + i * 2048), "l"(Ab + aoff[i] + koff) : "memory");
        #pragma unroll
        for (int i = 0; i < 8; i++)
            asm volatile("cp.async.cg.shared.global [%0], [%1], 16;"
                :: "r"(base + 16384 + sA0 + i * 2048),
                   "l"(Bb + boff0 + (uint32_t)i * (16u * K * 4u) + koff) : "memory");
        asm volatile("cp.async.commit_group;" ::: "memory");
    };

    float acc[4][8][4];
    #pragma unroll
    for (int a = 0; a < 4; a++)
        #pragma unroll
        for (int b = 0; b < 8; b++)
            #pragma unroll
            for (int c = 0; c < 4; c++) acc[a][b][c] = 0.f;

    fill(0, 0);
    fill(1, 1);
    fill(2, 2);

    // ldmatrix per-thread invariants
    const int aswz = lane & 7;
    const int arow = (lane & 7) + ((lane >> 3) & 1) * 8;
    const int ach  = (lane >> 4) & 1;
    const int brow = (lane & 7) + ((lane >> 4) & 1) * 8;
    const int bch  = (lane >> 3) & 1;

    for (int t = 0; t < T; t++) {
        int rem = T - 1 - t;
        if (rem >= 2)      asm volatile("cp.async.wait_group 2;" ::: "memory");
        else if (rem == 1) asm volatile("cp.async.wait_group 1;" ::: "memory");
        else               asm volatile("cp.async.wait_group 0;" ::: "memory");
        __syncthreads();

        const int slot = t % 3;
        const uint32_t ab = sb + slot * 32768;
        const uint32_t bbs = ab + 16384;
        #pragma unroll
        for (int kk = 0; kk < 4; kk++) {
            uint32_t ar[4][4], br[4][4];
            #pragma unroll
            for (int mi = 0; mi < 4; mi++) {
                uint32_t addr = ab + (uint32_t)((wm * 64 + mi * 16 + arow) * 128)
                              + (uint32_t)((((kk * 2 + ach) ^ aswz)) << 4);
                asm volatile("ldmatrix.sync.aligned.m8n8.x4.shared.b16 {%0,%1,%2,%3}, [%4];"
                    : "=r"(ar[mi][0]), "=r"(ar[mi][1]), "=r"(ar[mi][2]), "=r"(ar[mi][3])
                    : "r"(addr));
            }
            #pragma unroll
            for (int np = 0; np < 4; np++) {
                uint32_t addr = bbs + (uint32_t)((wn * 64 + np * 16 + brow) * 128)
                              + (uint32_t)((((kk * 2 + bch) ^ aswz)) << 4);
                asm volatile("ldmatrix.sync.aligned.m8n8.x4.shared.b16 {%0,%1,%2,%3}, [%4];"
                    : "=r"(br[np][0]), "=r"(br[np][1]), "=r"(br[np][2]), "=r"(br[np][3])
                    : "r"(addr));
            }
            if (EPI == 0) {
                #pragma unroll
                for (int mi = 0; mi < 4; mi++)
                    #pragma unroll
                    for (int j = 0; j < 4; j++) ar[mi][j] = tf32_rna(ar[mi][j]);
            }
            #pragma unroll
            for (int mi = 0; mi < 4; mi++)
                #pragma unroll
                for (int nj = 0; nj < 8; nj++) {
                    uint32_t b0 = br[nj >> 1][(nj & 1) * 2];
                    uint32_t b1 = br[nj >> 1][(nj & 1) * 2 + 1];
                    asm volatile(
                        "mma.sync.aligned.m16n8k8.row.col.f32.tf32.tf32.f32 "
                        "{%0,%1,%2,%3}, {%4,%5,%6,%7}, {%8,%9}, {%0,%1,%2,%3};"
                        : "+f"(acc[mi][nj][0]), "+f"(acc[mi][nj][1]),
                          "+f"(acc[mi][nj][2]), "+f"(acc[mi][nj][3])
                        : "r"(ar[mi][0]), "r"(ar[mi][1]), "r"(ar[mi][2]), "r"(ar[mi][3]),
                          "r"(b0), "r"(b1));
                }
        }
        __syncthreads();
        if (t + 3 < T) fill(slot, t + 3);
    }

    // ---- epilogue ----
    const int r4 = lane >> 2, l2 = (lane & 3) * 2;
    if (EPI < 2) {
        #pragma unroll
        for (int mi = 0; mi < 4; mi++)
            #pragma unroll
            for (int h = 0; h < 2; h++) {
                int m = R0 + wm * 64 + mi * 16 + r4 + h * 8;
                const float* brow_ = g_bias + (size_t)(m / SH) * P_;
                #pragma unroll
                for (int nj = 0; nj < 8; nj++) {
                    int n = N0 + wn * 64 + nj * 8 + l2;
                    float v0 = acc[mi][nj][h * 2 + 0];
                    float v1 = acc[mi][nj][h * 2 + 1];
                    if (EPI == 0) {
                        float2 bv = *(const float2*)(brow_ + n);
                        v0 += bv.x; v1 += bv.y;
                    }
                    float2 o;
                    o.x = tf32_rna_f(fast_tanh(v0));
                    o.y = tf32_rna_f(fast_tanh(v1));
                    *(float2*)(Cout + (size_t)m * P_ + n) = o;
                }
            }
    } else {
        __syncthreads();                    // smem reuse for reduction
        float* red = (float*)smem;          // [2][128]
        #pragma unroll
        for (int mi = 0; mi < 4; mi++)
            #pragma unroll
            for (int h = 0; h < 2; h++) {
                float sum = 0.f;
                #pragma unroll
                for (int nj = 0; nj < 8; nj++) {
                    int n = N0 + wn * 64 + nj * 8 + l2;
                    float v0 = fast_tanh(acc[mi][nj][h * 2 + 0]);
                    float v1 = fast_tanh(acc[mi][nj][h * 2 + 1]);
                    sum += v0 * __ldg(scorer + n) + v1 * __ldg(scorer + n + 1);
                }
                sum += __shfl_xor_sync(0xffffffffu, sum, 1);
                sum += __shfl_xor_sync(0xffffffffu, sum, 2);
                if ((lane & 3) == 0)
                    red[wn * 128 + wm * 64 + mi * 16 + r4 + h * 8] = sum;
            }
        __syncthreads();
        float tot = red[tid] + red[128 + tid];
        g_spart[(size_t)blockIdx.x * NROWS + R0 + tid] = tot;
    }
}

// ---------------------------------------------------------------------------
// masked softmax over s per batch; sums the 4 N-block score partials.
// ---------------------------------------------------------------------------
__global__ void __launch_bounds__(256) softmax_kernel(
    const void* __restrict__ mask_raw, float* __restrict__ out)
{
    __shared__ float red[256];
    const int b = blockIdx.x;
    const int s = threadIdx.x;
    const int mode = g_mask_mode;
    float e = 0.f;
    if (s < SH) {
        bool m;
        int idx = b * S_ + s;
        if (mode == 0)      m = ((const int*)mask_raw)[idx] != 0;
        else if (mode == 1) m = ((const float*)mask_raw)[idx] != 0.f;
        else                m = ((const unsigned char*)mask_raw)[idx] != 0;
        int r = b * SH + s;
        float sc = g_spart[r] + g_spart[NROWS + r] + g_spart[2 * NROWS + r] + g_spart[3 * NROWS + r];
        e = m ? expf(sc) : 0.f;
    }
    red[s] = e;
    __syncthreads();
    #pragma unroll
    for (int o = 128; o > 0; o >>= 1) {
        if (s < o) red[s] += red[s + o];
        __syncthreads();
    }
    float inv = 1.f / (red[0] + EPS_);
    if (s < SH) out[b * SH + s] = e * inv;
}

// ---------------------------------------------------------------------------
extern "C" void kernel_launch(void* const* d_in, const int* in_sizes, int n_in,
                              void* d_out, int out_size)
{
    // Resolve inputs by element count (robust to metadata ordering).
    int xi = -1, si = -1, mi = -1;
    int q[4] = {-1, -1, -1, -1};
    int nq = 0;
    for (int i = 0; i < n_in; i++) {
        long long sz = in_sizes[i];
        if (sz == (long long)B_ * S_ * D_)      xi = i;
        else if (sz == P_)                      si = i;
        else if (sz == (long long)B_ * S_)      mi = i;
        else if (sz == (long long)D_ * P_ && nq < 4) q[nq++] = i;
    }
    if (xi < 0 || si < 0 || mi < 0 || nq != 4) {
        xi = 0; q[0] = 1; q[1] = 2; q[2] = 3; q[3] = 4; si = 5; mi = 6;
    }
    const float *w_head, *w_prep, *w_child, *hid;
    if (xi == 0) {
        w_head = (const float*)d_in[q[0]];
        w_prep = (const float*)d_in[q[1]];
        w_child = (const float*)d_in[q[2]];
        hid    = (const float*)d_in[q[3]];
    } else {
        hid    = (const float*)d_in[q[0]];
        w_child = (const float*)d_in[q[1]];
        w_head = (const float*)d_in[q[2]];
        w_prep = (const float*)d_in[q[3]];
    }
    const float* x = (const float*)d_in[xi];
    const float* scorer = (const float*)d_in[si];
    const void* mask = d_in[mi];
    float* out = (float*)d_out;

    float *w1t_p, *h0t_p, *h1t_p, *c0_p, *c1_p;
    cudaGetSymbolAddress((void**)&w1t_p, g_w1t);
    cudaGetSymbolAddress((void**)&h0t_p, g_h0t);
    cudaGetSymbolAddress((void**)&h1t_p, g_h1t);
    cudaGetSymbolAddress((void**)&c0_p,  g_c0);
    cudaGetSymbolAddress((void**)&c1_p,  g_c1);

    cudaFuncSetAttribute(gemm_tf32<1024,0>, cudaFuncAttributeMaxDynamicSharedMemorySize, GSMEM);
    cudaFuncSetAttribute(gemm_tf32<512,1>,  cudaFuncAttributeMaxDynamicSharedMemorySize, GSMEM);
    cudaFuncSetAttribute(gemm_tf32<512,2>,  cudaFuncAttributeMaxDynamicSharedMemorySize, GSMEM);

    mask_probe_kernel<<<1, 256>>>((const unsigned int*)mask);
    transpose_all<<<dim3(P_/32, D_/32, 3), 256>>>(w_head, hid);
    bias_kernel<<<dim3(P_/128, B_/4), 128>>>(x, w_prep, w_child);

    gemm_tf32<1024,0><<<dim3(4, NROWS/128), 128, GSMEM>>>(x,    w1t_p, scorer, c0_p);
    gemm_tf32<512,1> <<<dim3(4, NROWS/128), 128, GSMEM>>>(c0_p, h0t_p, scorer, c1_p);
    gemm_tf32<512,2> <<<dim3(4, NROWS/128), 128, GSMEM>>>(c1_p, h1t_p, scorer, nullptr);

    softmax_kernel<<<B_, 256>>>(mask, out);
}

// round 10
// speedup vs baseline: 1.4979x; 1.3120x over previous
#include <cuda_runtime.h>
#include <cuda_bf16.h>
#include <cstdint>
#include <cstddef>

// Problem constants
#define B_   256
#define S_   256
#define D_   1024
#define P_   512
#define SH   254
#define NROWS (B_*SH)       // 65024
#define EPS_ 1e-7f

// Scratch (__device__ globals: allocation-free rule)
__device__ float g_bias[B_*P_];
__device__ float g_spart[4*NROWS];                    // per-N-block score partials
__device__ int   g_mask_mode;
__device__ __align__(1024) __nv_bfloat16 g_xb[(size_t)B_*S_*D_];  // x in bf16
__device__ __align__(1024) __nv_bfloat16 g_w1t[(size_t)P_*D_];    // proj_head^T bf16
__device__ __align__(1024) __nv_bfloat16 g_h0t[(size_t)P_*P_];    // hidden0^T bf16
__device__ __align__(1024) __nv_bfloat16 g_h1t[(size_t)P_*P_];    // hidden1^T bf16
__device__ __align__(1024) __nv_bfloat16 g_c0[(size_t)NROWS*P_];  // act after stage 1
__device__ __align__(1024) __nv_bfloat16 g_c1[(size_t)NROWS*P_];  // act after stage 2

__device__ __forceinline__ float fast_tanh(float x) {
    float y; asm("tanh.approx.f32 %0, %1;" : "=f"(y) : "f"(x)); return y;
}
__device__ __forceinline__ uint32_t smem_u32(const void* p) {
    uint32_t a;
    asm("{ .reg .u64 t; cvta.to.shared.u64 t, %1; cvt.u32.u64 %0, t; }" : "=r"(a) : "l"(p));
    return a;
}

// ---------------------------------------------------------------------------
// mask dtype probe (reads only first 65536 bytes; deterministic)
// ---------------------------------------------------------------------------
__global__ void __launch_bounds__(256) mask_probe_kernel(const unsigned int* __restrict__ m)
{
    __shared__ int s01, sf;
    if (threadIdx.x == 0) { s01 = 1; sf = 1; }
    __syncthreads();
    bool ok01 = true, okf = true;
    #pragma unroll 4
    for (int it = 0; it < 64; it++) {
        unsigned int v = m[threadIdx.x + it * 256];
        if (v > 1u) ok01 = false;
        if (v != 0u && v != 0x3F800000u) okf = false;
    }
    if (!ok01) atomicAnd(&s01, 0);
    if (!okf)  atomicAnd(&sf, 0);
    __syncthreads();
    if (threadIdx.x == 0) g_mask_mode = s01 ? 0 : (sf ? 1 : 2);
}

// ---------------------------------------------------------------------------
// convert x -> bf16, same layout. 67.1M elems, 8 per thread-iter (float4 x2 -> 16B).
// ---------------------------------------------------------------------------
__global__ void __launch_bounds__(256) convert_x_kernel(const float4* __restrict__ x4)
{
    const size_t n4 = (size_t)B_ * S_ * D_ / 8;     // 8.39M iterations of 8 elems
    uint4* dst = (uint4*)g_xb;
    for (size_t i = blockIdx.x * 256 + threadIdx.x; i < n4; i += (size_t)gridDim.x * 256) {
        float4 a = x4[i * 2], b = x4[i * 2 + 1];
        __nv_bfloat162 p0 = __floats2bfloat162_rn(a.x, a.y);
        __nv_bfloat162 p1 = __floats2bfloat162_rn(a.z, a.w);
        __nv_bfloat162 p2 = __floats2bfloat162_rn(b.x, b.y);
        __nv_bfloat162 p3 = __floats2bfloat162_rn(b.z, b.w);
        uint4 o;
        o.x = *(uint32_t*)&p0; o.y = *(uint32_t*)&p1;
        o.z = *(uint32_t*)&p2; o.w = *(uint32_t*)&p3;
        dst[i] = o;
    }
}

// ---------------------------------------------------------------------------
// One launch: transpose all 3 weight matrices W[K][N] -> Wt[N][K], to bf16.
// ---------------------------------------------------------------------------
__global__ void __launch_bounds__(256) transpose_all(
    const float* __restrict__ w_head, const float* __restrict__ hid)
{
    const int z = blockIdx.z;
    const int K = (z == 0) ? D_ : P_;
    if (blockIdx.y * 32 >= K) return;
    const float* src = (z == 0) ? w_head : (hid + (size_t)(z - 1) * P_ * P_);
    __nv_bfloat16* dst = (z == 0) ? g_w1t : ((z == 1) ? g_h0t : g_h1t);

    __shared__ float t[32][33];
    int k0 = blockIdx.y * 32, n0 = blockIdx.x * 32;
    int tx = threadIdx.x & 31, ty = threadIdx.x >> 5;   // 32 x 8
    #pragma unroll
    for (int i = 0; i < 32; i += 8)
        t[ty + i][tx] = src[(size_t)(k0 + ty + i) * P_ + n0 + tx];
    __syncthreads();
    #pragma unroll
    for (int i = 0; i < 32; i += 8)
        dst[(size_t)(n0 + ty + i) * K + k0 + tx] = __float2bfloat16_rn(t[tx][ty + i]);
}

// ---------------------------------------------------------------------------
// bias kernel: bias[b][p] = prep·proj_prep[:,p] + child·proj_child[:,p] (fp32)
// ---------------------------------------------------------------------------
__global__ void __launch_bounds__(128) bias_kernel(
    const float* __restrict__ x,
    const float* __restrict__ wp,
    const float* __restrict__ wc)
{
    __shared__ float sP[4][D_];
    __shared__ float sC[4][D_];
    const int tid = threadIdx.x;
    const int b0  = blockIdx.y * 4;
    #pragma unroll
    for (int it = 0; it < 16; it++) {
        int idx  = tid + it * 128;
        int row  = idx >> 8;
        int col4 = idx & 255;
        int bb   = b0 + (row >> 1);
        int which = row & 1;
        const float* src = x + ((size_t)bb * S_ + (S_ - 2) + which) * D_;
        float4 v = *(const float4*)(src + col4 * 4);
        float* dst = which ? &sC[row >> 1][0] : &sP[row >> 1][0];
        *(float4*)(dst + col4 * 4) = v;
    }
    __syncthreads();
    const int p = blockIdx.x * 128 + tid;
    float acc[4] = {0.f, 0.f, 0.f, 0.f};
    #pragma unroll 4
    for (int d = 0; d < D_; d++) {
        float a = wp[(size_t)d * P_ + p];
        float c = wc[(size_t)d * P_ + p];
        #pragma unroll
        for (int j = 0; j < 4; j++) acc[j] += sP[j][d] * a + sC[j][d] * c;
    }
    #pragma unroll
    for (int j = 0; j < 4; j++)
        g_bias[(size_t)(b0 + j) * P_ + p] = acc[j];
}

// ---------------------------------------------------------------------------
// bf16 mma.sync GEMM stage. CTA = 128 threads (4 warps, 2M x 2N), tile 128x128,
// warp tile 64x64, BK=64 bf16 (128B rows), 3-stage cp.async, 96KB -> 2 CTAs/SM.
// mma m16n8k16, fp32 accumulate.
// EPI: 0 = +bias,tanh -> bf16 Cout ; 1 = tanh -> bf16 Cout ; 2 = tanh + scorer partial
// smem per stage (32768 B): A[128][64bf16] @0, B[128][64bf16] @16384. XOR swizzle.
// ---------------------------------------------------------------------------
#define GSMEM 98304

template<int K, int EPI>
__global__ void __launch_bounds__(128, 2) gemm_bf16(
    const __nv_bfloat16* __restrict__ A,
    const __nv_bfloat16* __restrict__ BT,
    const float* __restrict__ scorer,
    __nv_bfloat16* __restrict__ Cout)
{
    constexpr int T = K / 64;
    extern __shared__ __align__(1024) char smem[];
    const uint32_t sb = smem_u32(smem);
    const int tid = threadIdx.x, lane = tid & 31, wid = tid >> 5;
    const int wm = wid >> 1, wn = wid & 1;
    const int N0 = blockIdx.x * 128, R0 = blockIdx.y * 128;

    // ---- cp.async offsets. chunk cc = tid&7 (16B = 8 bf16), base row r0 = tid>>3.
    // A/B rows r0 + 16i (i<8); swizzle constant across i (16 ≡ 0 mod 8).
    const int r0 = tid >> 3, cc = tid & 7;
    const uint32_t sA0 = (uint32_t)(r0 * 128 + ((cc ^ (r0 & 7)) << 4));
    uint32_t aoff[8];   // byte offsets
    #pragma unroll
    for (int i = 0; i < 8; i++) {
        int r = R0 + r0 + i * 16;
        if (EPI == 0) {
            int b = r / SH; int s2 = r - b * SH;
            aoff[i] = (uint32_t)(((b * S_ + s2) * D_ + cc * 8) * 2);
        } else {
            aoff[i] = (uint32_t)((r * K + cc * 8) * 2);
        }
    }
    const uint32_t boff0 = (uint32_t)(((N0 + r0) * K + cc * 8) * 2);
    const char* Ab = (const char*)A;
    const char* Bb = (const char*)BT;

    auto fill = [&](int slot, int kt) {
        uint32_t base = sb + slot * 32768;
        uint32_t koff = (uint32_t)kt * 128;   // 64 bf16 = 128 bytes
        #pragma unroll
        for (int i = 0; i < 8; i++)
            asm volatile("cp.async.cg.shared.global [%0], [%1], 16;"
                :: "r"(base + sA0 + i * 2048), "l"(Ab + aoff[i] + koff) : "memory");
        #pragma unroll
        for (int i = 0; i < 8; i++)
            asm volatile("cp.async.cg.shared.global [%0], [%1], 16;"
                :: "r"(base + 16384 + sA0 + i * 2048),
                   "l"(Bb + boff0 + (uint32_t)i * (16u * K * 2u) + koff) : "memory");
        asm volatile("cp.async.commit_group;" ::: "memory");
    };

    float acc[4][8][4];
    #pragma unroll
    for (int a = 0; a < 4; a++)
        #pragma unroll
        for (int b = 0; b < 8; b++)
            #pragma unroll
            for (int c = 0; c < 4; c++) acc[a][b][c] = 0.f;

    fill(0, 0);
    fill(1, 1);
    fill(2, 2);

    // ldmatrix per-thread invariants (canonical m16n8k16 pattern)
    const int lrow = lane & 15;           // row within 16-row tile
    const int lhalf = lane >> 4;          // 16B-chunk half (k0-7 vs k8-15)
    const int lswz = lrow & 7;

    for (int t = 0; t < T; t++) {
        int rem = T - 1 - t;
        if (rem >= 2)      asm volatile("cp.async.wait_group 2;" ::: "memory");
        else if (rem == 1) asm volatile("cp.async.wait_group 1;" ::: "memory");
        else               asm volatile("cp.async.wait_group 0;" ::: "memory");
        __syncthreads();

        const int slot = t % 3;
        const uint32_t ab = sb + slot * 32768;
        const uint32_t bbs = ab + 16384;
        #pragma unroll
        for (int kk = 0; kk < 4; kk++) {      // 4 x k16 per 64-chunk
            const uint32_t coff = (uint32_t)(((kk * 2 + lhalf) ^ lswz) << 4);
            uint32_t ar[4][4], br[4][4];
            #pragma unroll
            for (int mi = 0; mi < 4; mi++) {
                uint32_t addr = ab + (uint32_t)((wm * 64 + mi * 16 + lrow) * 128) + coff;
                asm volatile("ldmatrix.sync.aligned.m8n8.x4.shared.b16 {%0,%1,%2,%3}, [%4];"
                    : "=r"(ar[mi][0]), "=r"(ar[mi][1]), "=r"(ar[mi][2]), "=r"(ar[mi][3])
                    : "r"(addr));
            }
            #pragma unroll
            for (int np = 0; np < 4; np++) {
                uint32_t addr = bbs + (uint32_t)((wn * 64 + np * 16 + lrow) * 128) + coff;
                asm volatile("ldmatrix.sync.aligned.m8n8.x4.shared.b16 {%0,%1,%2,%3}, [%4];"
                    : "=r"(br[np][0]), "=r"(br[np][1]), "=r"(br[np][2]), "=r"(br[np][3])
                    : "r"(addr));
            }
            #pragma unroll
            for (int mi = 0; mi < 4; mi++)
                #pragma unroll
                for (int nj = 0; nj < 8; nj++) {
                    uint32_t b0 = br[nj >> 1][nj & 1];        // k0-7
                    uint32_t b1 = br[nj >> 1][(nj & 1) + 2];  // k8-15
                    asm volatile(
                        "mma.sync.aligned.m16n8k16.row.col.f32.bf16.bf16.f32 "
                        "{%0,%1,%2,%3}, {%4,%5,%6,%7}, {%8,%9}, {%0,%1,%2,%3};"
                        : "+f"(acc[mi][nj][0]), "+f"(acc[mi][nj][1]),
                          "+f"(acc[mi][nj][2]), "+f"(acc[mi][nj][3])
                        : "r"(ar[mi][0]), "r"(ar[mi][1]), "r"(ar[mi][2]), "r"(ar[mi][3]),
                          "r"(b0), "r"(b1));
                }
        }
        __syncthreads();
        if (t + 3 < T) fill(slot, t + 3);
    }

    // ---- epilogue ----
    const int r4 = lane >> 2, l2 = (lane & 3) * 2;
    if (EPI < 2) {
        #pragma unroll
        for (int mi = 0; mi < 4; mi++)
            #pragma unroll
            for (int h = 0; h < 2; h++) {
                int m = R0 + wm * 64 + mi * 16 + r4 + h * 8;
                const float* brow_ = g_bias + (size_t)(m / SH) * P_;
                #pragma unroll
                for (int nj = 0; nj < 8; nj++) {
                    int n = N0 + wn * 64 + nj * 8 + l2;
                    float v0 = acc[mi][nj][h * 2 + 0];
                    float v1 = acc[mi][nj][h * 2 + 1];
                    if (EPI == 0) {
                        float2 bv = *(const float2*)(brow_ + n);
                        v0 += bv.x; v1 += bv.y;
                    }
                    __nv_bfloat162 o = __floats2bfloat162_rn(fast_tanh(v0), fast_tanh(v1));
                    *(uint32_t*)(Cout + (size_t)m * P_ + n) = *(uint32_t*)&o;
                }
            }
    } else {
        __syncthreads();                    // smem reuse for reduction
        float* red = (float*)smem;          // [2][128]
        #pragma unroll
        for (int mi = 0; mi < 4; mi++)
            #pragma unroll
            for (int h = 0; h < 2; h++) {
                float sum = 0.f;
                #pragma unroll
                for (int nj = 0; nj < 8; nj++) {
                    int n = N0 + wn * 64 + nj * 8 + l2;
                    float v0 = fast_tanh(acc[mi][nj][h * 2 + 0]);
                    float v1 = fast_tanh(acc[mi][nj][h * 2 + 1]);
                    sum += v0 * __ldg(scorer + n) + v1 * __ldg(scorer + n + 1);
                }
                sum += __shfl_xor_sync(0xffffffffu, sum, 1);
                sum += __shfl_xor_sync(0xffffffffu, sum, 2);
                if ((lane & 3) == 0)
                    red[wn * 128 + wm * 64 + mi * 16 + r4 + h * 8] = sum;
            }
        __syncthreads();
        float tot = red[tid] + red[128 + tid];
        g_spart[(size_t)blockIdx.x * NROWS + R0 + tid] = tot;
    }
}

// ---------------------------------------------------------------------------
// masked softmax over s per batch; sums the 4 N-block score partials.
// ---------------------------------------------------------------------------
__global__ void __launch_bounds__(256) softmax_kernel(
    const void* __restrict__ mask_raw, float* __restrict__ out)
{
    __shared__ float red[256];
    const int b = blockIdx.x;
    const int s = threadIdx.x;
    const int mode = g_mask_mode;
    float e = 0.f;
    if (s < SH) {
        bool m;
        int idx = b * S_ + s;
        if (mode == 0)      m = ((const int*)mask_raw)[idx] != 0;
        else if (mode == 1) m = ((const float*)mask_raw)[idx] != 0.f;
        else                m = ((const unsigned char*)mask_raw)[idx] != 0;
        int r = b * SH + s;
        float sc = g_spart[r] + g_spart[NROWS + r] + g_spart[2 * NROWS + r] + g_spart[3 * NROWS + r];
        e = m ? expf(sc) : 0.f;
    }
    red[s] = e;
    __syncthreads();
    #pragma unroll
    for (int o = 128; o > 0; o >>= 1) {
        if (s < o) red[s] += red[s + o];
        __syncthreads();
    }
    float inv = 1.f / (red[0] + EPS_);
    if (s < SH) out[b * SH + s] = e * inv;
}

// ---------------------------------------------------------------------------
extern "C" void kernel_launch(void* const* d_in, const int* in_sizes, int n_in,
                              void* d_out, int out_size)
{
    // Resolve inputs by element count (robust to metadata ordering).
    int xi = -1, si = -1, mi = -1;
    int q[4] = {-1, -1, -1, -1};
    int nq = 0;
    for (int i = 0; i < n_in; i++) {
        long long sz = in_sizes[i];
        if (sz == (long long)B_ * S_ * D_)      xi = i;
        else if (sz == P_)                      si = i;
        else if (sz == (long long)B_ * S_)      mi = i;
        else if (sz == (long long)D_ * P_ && nq < 4) q[nq++] = i;
    }
    if (xi < 0 || si < 0 || mi < 0 || nq != 4) {
        xi = 0; q[0] = 1; q[1] = 2; q[2] = 3; q[3] = 4; si = 5; mi = 6;
    }
    const float *w_head, *w_prep, *w_child, *hid;
    if (xi == 0) {
        w_head = (const float*)d_in[q[0]];
        w_prep = (const float*)d_in[q[1]];
        w_child = (const float*)d_in[q[2]];
        hid    = (const float*)d_in[q[3]];
    } else {
        hid    = (const float*)d_in[q[0]];
        w_child = (const float*)d_in[q[1]];
        w_head = (const float*)d_in[q[2]];
        w_prep = (const float*)d_in[q[3]];
    }
    const float* x = (const float*)d_in[xi];
    const float* scorer = (const float*)d_in[si];
    const void* mask = d_in[mi];
    float* out = (float*)d_out;

    __nv_bfloat16 *xb_p, *w1t_p, *h0t_p, *h1t_p, *c0_p, *c1_p;
    cudaGetSymbolAddress((void**)&xb_p,  g_xb);
    cudaGetSymbolAddress((void**)&w1t_p, g_w1t);
    cudaGetSymbolAddress((void**)&h0t_p, g_h0t);
    cudaGetSymbolAddress((void**)&h1t_p, g_h1t);
    cudaGetSymbolAddress((void**)&c0_p,  g_c0);
    cudaGetSymbolAddress((void**)&c1_p,  g_c1);

    cudaFuncSetAttribute(gemm_bf16<1024,0>, cudaFuncAttributeMaxDynamicSharedMemorySize, GSMEM);
    cudaFuncSetAttribute(gemm_bf16<512,1>,  cudaFuncAttributeMaxDynamicSharedMemorySize, GSMEM);
    cudaFuncSetAttribute(gemm_bf16<512,2>,  cudaFuncAttributeMaxDynamicSharedMemorySize, GSMEM);

    mask_probe_kernel<<<1, 256>>>((const unsigned int*)mask);
    convert_x_kernel<<<4096, 256>>>((const float4*)x);
    transpose_all<<<dim3(P_/32, D_/32, 3), 256>>>(w_head, hid);
    bias_kernel<<<dim3(P_/128, B_/4), 128>>>(x, w_prep, w_child);

    gemm_bf16<1024,0><<<dim3(4, NROWS/128), 128, GSMEM>>>(xb_p, w1t_p, scorer, c0_p);
    gemm_bf16<512,1> <<<dim3(4, NROWS/128), 128, GSMEM>>>(c0_p, h0t_p, scorer, c1_p);
    gemm_bf16<512,2> <<<dim3(4, NROWS/128), 128, GSMEM>>>(c1_p, h1t_p, scorer, nullptr);

    softmax_kernel<<<B_, 256>>>(mask, out);
}

// round 13
// speedup vs baseline: 1.7091x; 1.1410x over previous
#include <cuda_runtime.h>
#include <cuda_bf16.h>
#include <cstdint>
#include <cstddef>

// Problem constants
#define B_   256
#define S_   256
#define D_   1024
#define P_   512
#define SH   254
#define NROWS (B_*SH)       // 65024
#define EPS_ 1e-7f

// Scratch (__device__ globals: allocation-free rule)
__device__ float g_bias[B_*P_];
__device__ float g_spart[4*NROWS];                    // per-N-block score partials
__device__ int   g_mask_mode;
__device__ __align__(1024) __nv_bfloat16 g_xb[(size_t)B_*S_*D_];  // x in bf16
__device__ __align__(1024) __nv_bfloat16 g_w1t[(size_t)P_*D_];    // proj_head^T bf16
__device__ __align__(1024) __nv_bfloat16 g_h0t[(size_t)P_*P_];    // hidden0^T bf16
__device__ __align__(1024) __nv_bfloat16 g_h1t[(size_t)P_*P_];    // hidden1^T bf16
__device__ __align__(1024) __nv_bfloat16 g_c0[(size_t)NROWS*P_];  // act after stage 1
__device__ __align__(1024) __nv_bfloat16 g_c1[(size_t)NROWS*P_];  // act after stage 2

__device__ __forceinline__ float fast_tanh(float x) {
    float y; asm("tanh.approx.f32 %0, %1;" : "=f"(y) : "f"(x)); return y;
}
__device__ __forceinline__ uint32_t smem_u32(const void* p) {
    uint32_t a;
    asm("{ .reg .u64 t; cvta.to.shared.u64 t, %1; cvt.u32.u64 %0, t; }" : "=r"(a) : "l"(p));
    return a;
}

// ---------------------------------------------------------------------------
// mask dtype probe (reads only first 65536 bytes; deterministic)
// ---------------------------------------------------------------------------
__global__ void __launch_bounds__(256) mask_probe_kernel(const unsigned int* __restrict__ m)
{
    __shared__ int s01, sf;
    if (threadIdx.x == 0) { s01 = 1; sf = 1; }
    __syncthreads();
    bool ok01 = true, okf = true;
    #pragma unroll 4
    for (int it = 0; it < 64; it++) {
        unsigned int v = m[threadIdx.x + it * 256];
        if (v > 1u) ok01 = false;
        if (v != 0u && v != 0x3F800000u) okf = false;
    }
    if (!ok01) atomicAnd(&s01, 0);
    if (!okf)  atomicAnd(&sf, 0);
    __syncthreads();
    if (threadIdx.x == 0) g_mask_mode = s01 ? 0 : (sf ? 1 : 2);
}

// ---------------------------------------------------------------------------
// convert x -> bf16, same layout. 67.1M elems, 8 per thread-iter.
// ---------------------------------------------------------------------------
__global__ void __launch_bounds__(256) convert_x_kernel(const float4* __restrict__ x4)
{
    const size_t n4 = (size_t)B_ * S_ * D_ / 8;
    uint4* dst = (uint4*)g_xb;
    for (size_t i = blockIdx.x * 256 + threadIdx.x; i < n4; i += (size_t)gridDim.x * 256) {
        float4 a = x4[i * 2], b = x4[i * 2 + 1];
        __nv_bfloat162 p0 = __floats2bfloat162_rn(a.x, a.y);
        __nv_bfloat162 p1 = __floats2bfloat162_rn(a.z, a.w);
        __nv_bfloat162 p2 = __floats2bfloat162_rn(b.x, b.y);
        __nv_bfloat162 p3 = __floats2bfloat162_rn(b.z, b.w);
        uint4 o;
        o.x = *(uint32_t*)&p0; o.y = *(uint32_t*)&p1;
        o.z = *(uint32_t*)&p2; o.w = *(uint32_t*)&p3;
        dst[i] = o;
    }
}

// ---------------------------------------------------------------------------
// One launch: transpose all 3 weight matrices W[K][N] -> Wt[N][K], to bf16.
// ---------------------------------------------------------------------------
__global__ void __launch_bounds__(256) transpose_all(
    const float* __restrict__ w_head, const float* __restrict__ hid)
{
    const int z = blockIdx.z;
    const int K = (z == 0) ? D_ : P_;
    if (blockIdx.y * 32 >= K) return;
    const float* src = (z == 0) ? w_head : (hid + (size_t)(z - 1) * P_ * P_);
    __nv_bfloat16* dst = (z == 0) ? g_w1t : ((z == 1) ? g_h0t : g_h1t);

    __shared__ float t[32][33];
    int k0 = blockIdx.y * 32, n0 = blockIdx.x * 32;
    int tx = threadIdx.x & 31, ty = threadIdx.x >> 5;   // 32 x 8
    #pragma unroll
    for (int i = 0; i < 32; i += 8)
        t[ty + i][tx] = src[(size_t)(k0 + ty + i) * P_ + n0 + tx];
    __syncthreads();
    #pragma unroll
    for (int i = 0; i < 32; i += 8)
        dst[(size_t)(n0 + ty + i) * K + k0 + tx] = __float2bfloat16_rn(t[tx][ty + i]);
}

// ---------------------------------------------------------------------------
// bias kernel v2: bias[b][p] = prep·wp[:,p] + child·wc[:,p] (fp32).
// grid (4 pblk, 64 bblk), 512 threads: tid&127 = p-lane, tid>>7 = d-quarter.
// 4-way d-split quadruples warp count (latency fix for the 135us v1);
// in-block smem reduction, no atomics (graph-replay deterministic).
// ---------------------------------------------------------------------------
__global__ void __launch_bounds__(512) bias_kernel(
    const float* __restrict__ x,
    const float* __restrict__ wp,
    const float* __restrict__ wc)
{
    __shared__ __align__(16) float sP[4][D_];   // 16KB
    __shared__ __align__(16) float sC[4][D_];   // 16KB
    __shared__ float red[4][4][128];            // 8KB  [quarter][batch][p]
    const int tid = threadIdx.x;
    const int b0  = blockIdx.y * 4;

    // stage 8 rows (4 prep + 4 child): 2048 float4 by 512 threads
    #pragma unroll
    for (int it = 0; it < 4; it++) {
        int idx  = tid + it * 512;
        int row  = idx >> 8;              // 0..7
        int col4 = idx & 255;
        int bb   = b0 + (row >> 1);
        int which = row & 1;
        const float* src = x + ((size_t)bb * S_ + (S_ - 2) + which) * D_;
        float4 v = *(const float4*)(src + col4 * 4);
        float* dst = which ? &sC[row >> 1][0] : &sP[row >> 1][0];
        *(float4*)(dst + col4 * 4) = v;
    }
    __syncthreads();

    const int pl = tid & 127;
    const int q  = tid >> 7;              // d-quarter 0..3
    const int p  = blockIdx.x * 128 + pl;
    const int d0 = q * 256;

    float acc[4] = {0.f, 0.f, 0.f, 0.f};
    #pragma unroll 4
    for (int d = d0; d < d0 + 256; d++) {
        float a = wp[(size_t)d * P_ + p];
        float c = wc[(size_t)d * P_ + p];
        #pragma unroll
        for (int j = 0; j < 4; j++)
            acc[j] += sP[j][d] * a + sC[j][d] * c;
    }
    #pragma unroll
    for (int j = 0; j < 4; j++) red[q][j][pl] = acc[j];
    __syncthreads();
    if (q == 0) {
        #pragma unroll
        for (int j = 0; j < 4; j++) {
            float v = red[0][j][pl] + red[1][j][pl] + red[2][j][pl] + red[3][j][pl];
            g_bias[(size_t)(b0 + j) * P_ + p] = v;
        }
    }
}

// ---------------------------------------------------------------------------
// bf16 mma.sync GEMM stage. CTA = 128 threads (4 warps, 2M x 2N), tile 128x128,
// warp tile 64x64, BK=64 bf16 (128B rows), 3-stage cp.async, 96KB -> 2 CTAs/SM.
// mma m16n8k16, fp32 accumulate.
// EPI: 0 = +bias,tanh -> bf16 Cout ; 1 = tanh -> bf16 Cout ; 2 = tanh + scorer partial
// ---------------------------------------------------------------------------
#define GSMEM 98304

template<int K, int EPI>
__global__ void __launch_bounds__(128, 2) gemm_bf16(
    const __nv_bfloat16* __restrict__ A,
    const __nv_bfloat16* __restrict__ BT,
    const float* __restrict__ scorer,
    __nv_bfloat16* __restrict__ Cout)
{
    constexpr int T = K / 64;
    extern __shared__ __align__(1024) char smem[];
    const uint32_t sb = smem_u32(smem);
    const int tid = threadIdx.x, lane = tid & 31, wid = tid >> 5;
    const int wm = wid >> 1, wn = wid & 1;
    const int N0 = blockIdx.x * 128, R0 = blockIdx.y * 128;

    const int r0 = tid >> 3, cc = tid & 7;
    const uint32_t sA0 = (uint32_t)(r0 * 128 + ((cc ^ (r0 & 7)) << 4));
    uint32_t aoff[8];   // byte offsets
    #pragma unroll
    for (int i = 0; i < 8; i++) {
        int r = R0 + r0 + i * 16;
        if (EPI == 0) {
            int b = r / SH; int s2 = r - b * SH;
            aoff[i] = (uint32_t)(((b * S_ + s2) * D_ + cc * 8) * 2);
        } else {
            aoff[i] = (uint32_t)((r * K + cc * 8) * 2);
        }
    }
    const uint32_t boff0 = (uint32_t)(((N0 + r0) * K + cc * 8) * 2);
    const char* Ab = (const char*)A;
    const char* Bb = (const char*)BT;

    auto fill = [&](int slot, int kt) {
        uint32_t base = sb + slot * 32768;
        uint32_t koff = (uint32_t)kt * 128;   // 64 bf16 = 128 bytes
        #pragma unroll
        for (int i = 0; i < 8; i++)
            asm volatile("cp.async.cg.shared.global [%0], [%1], 16;"
                :: "r"(base + sA0 + i * 2048), "l"(Ab + aoff[i] + koff) : "memory");
        #pragma unroll
        for (int i = 0; i < 8; i++)
            asm volatile("cp.async.cg.shared.global [%0], [%1], 16;"
                :: "r"(base + 16384 + sA0 + i * 2048),
                   "l"(Bb + boff0 + (uint32_t)i * (16u * K * 2u) + koff) : "memory");
        asm volatile("cp.async.commit_group;" ::: "memory");
    };

    float acc[4][8][4];
    #pragma unroll
    for (int a = 0; a < 4; a++)
        #pragma unroll
        for (int b = 0; b < 8; b++)
            #pragma unroll
            for (int c = 0; c < 4; c++) acc[a][b][c] = 0.f;

    fill(0, 0);
    fill(1, 1);
    fill(2, 2);

    const int lrow = lane & 15;
    const int lhalf = lane >> 4;
    const int lswz = lrow & 7;

    for (int t = 0; t < T; t++) {
        int rem = T - 1 - t;
        if (rem >= 2)      asm volatile("cp.async.wait_group 2;" ::: "memory");
        else if (rem == 1) asm volatile("cp.async.wait_group 1;" ::: "memory");
        else               asm volatile("cp.async.wait_group 0;" ::: "memory");
        __syncthreads();

        const int slot = t % 3;
        const uint32_t ab = sb + slot * 32768;
        const uint32_t bbs = ab + 16384;
        #pragma unroll
        for (int kk = 0; kk < 4; kk++) {
            const uint32_t coff = (uint32_t)(((kk * 2 + lhalf) ^ lswz) << 4);
            uint32_t ar[4][4], br[4][4];
            #pragma unroll
            for (int mi = 0; mi < 4; mi++) {
                uint32_t addr = ab + (uint32_t)((wm * 64 + mi * 16 + lrow) * 128) + coff;
                asm volatile("ldmatrix.sync.aligned.m8n8.x4.shared.b16 {%0,%1,%2,%3}, [%4];"
                    : "=r"(ar[mi][0]), "=r"(ar[mi][1]), "=r"(ar[mi][2]), "=r"(ar[mi][3])
                    : "r"(addr));
            }
            #pragma unroll
            for (int np = 0; np < 4; np++) {
                uint32_t addr = bbs + (uint32_t)((wn * 64 + np * 16 + lrow) * 128) + coff;
                asm volatile("ldmatrix.sync.aligned.m8n8.x4.shared.b16 {%0,%1,%2,%3}, [%4];"
                    : "=r"(br[np][0]), "=r"(br[np][1]), "=r"(br[np][2]), "=r"(br[np][3])
                    : "r"(addr));
            }
            #pragma unroll
            for (int mi = 0; mi < 4; mi++)
                #pragma unroll
                for (int nj = 0; nj < 8; nj++) {
                    uint32_t b0 = br[nj >> 1][nj & 1];
                    uint32_t b1 = br[nj >> 1][(nj & 1) + 2];
                    asm volatile(
                        "mma.sync.aligned.m16n8k16.row.col.f32.bf16.bf16.f32 "
                        "{%0,%1,%2,%3}, {%4,%5,%6,%7}, {%8,%9}, {%0,%1,%2,%3};"
                        : "+f"(acc[mi][nj][0]), "+f"(acc[mi][nj][1]),
                          "+f"(acc[mi][nj][2]), "+f"(acc[mi][nj][3])
                        : "r"(ar[mi][0]), "r"(ar[mi][1]), "r"(ar[mi][2]), "r"(ar[mi][3]),
                          "r"(b0), "r"(b1));
                }
        }
        __syncthreads();
        if (t + 3 < T) fill(slot, t + 3);
    }

    // ---- epilogue ----
    const int r4 = lane >> 2, l2 = (lane & 3) * 2;
    if (EPI < 2) {
        #pragma unroll
        for (int mi = 0; mi < 4; mi++)
            #pragma unroll
            for (int h = 0; h < 2; h++) {
                int m = R0 + wm * 64 + mi * 16 + r4 + h * 8;
                const float* brow_ = g_bias + (size_t)(m / SH) * P_;
                #pragma unroll
                for (int nj = 0; nj < 8; nj++) {
                    int n = N0 + wn * 64 + nj * 8 + l2;
                    float v0 = acc[mi][nj][h * 2 + 0];
                    float v1 = acc[mi][nj][h * 2 + 1];
                    if (EPI == 0) {
                        float2 bv = *(const float2*)(brow_ + n);
                        v0 += bv.x; v1 += bv.y;
                    }
                    __nv_bfloat162 o = __floats2bfloat162_rn(fast_tanh(v0), fast_tanh(v1));
                    *(uint32_t*)(Cout + (size_t)m * P_ + n) = *(uint32_t*)&o;
                }
            }
    } else {
        __syncthreads();                    // smem reuse for reduction
        float* red = (float*)smem;          // [2][128]
        #pragma unroll
        for (int mi = 0; mi < 4; mi++)
            #pragma unroll
            for (int h = 0; h < 2; h++) {
                float sum = 0.f;
                #pragma unroll
                for (int nj = 0; nj < 8; nj++) {
                    int n = N0 + wn * 64 + nj * 8 + l2;
                    float v0 = fast_tanh(acc[mi][nj][h * 2 + 0]);
                    float v1 = fast_tanh(acc[mi][nj][h * 2 + 1]);
                    sum += v0 * __ldg(scorer + n) + v1 * __ldg(scorer + n + 1);
                }
                sum += __shfl_xor_sync(0xffffffffu, sum, 1);
                sum += __shfl_xor_sync(0xffffffffu, sum, 2);
                if ((lane & 3) == 0)
                    red[wn * 128 + wm * 64 + mi * 16 + r4 + h * 8] = sum;
            }
        __syncthreads();
        float tot = red[tid] + red[128 + tid];
        g_spart[(size_t)blockIdx.x * NROWS + R0 + tid] = tot;
    }
}

// ---------------------------------------------------------------------------
// masked softmax over s per batch; sums the 4 N-block score partials.
// ---------------------------------------------------------------------------
__global__ void __launch_bounds__(256) softmax_kernel(
    const void* __restrict__ mask_raw, float* __restrict__ out)
{
    __shared__ float red[256];
    const int b = blockIdx.x;
    const int s = threadIdx.x;
    const int mode = g_mask_mode;
    float e = 0.f;
    if (s < SH) {
        bool m;
        int idx = b * S_ + s;
        if (mode == 0)      m = ((const int*)mask_raw)[idx] != 0;
        else if (mode == 1) m = ((const float*)mask_raw)[idx] != 0.f;
        else                m = ((const unsigned char*)mask_raw)[idx] != 0;
        int r = b * SH + s;
        float sc = g_spart[r] + g_spart[NROWS + r] + g_spart[2 * NROWS + r] + g_spart[3 * NROWS + r];
        e = m ? expf(sc) : 0.f;
    }
    red[s] = e;
    __syncthreads();
    #pragma unroll
    for (int o = 128; o > 0; o >>= 1) {
        if (s < o) red[s] += red[s + o];
        __syncthreads();
    }
    float inv = 1.f / (red[0] + EPS_);
    if (s < SH) out[b * SH + s] = e * inv;
}

// ---------------------------------------------------------------------------
extern "C" void kernel_launch(void* const* d_in, const int* in_sizes, int n_in,
                              void* d_out, int out_size)
{
    // Resolve inputs by element count (robust to metadata ordering).
    int xi = -1, si = -1, mi = -1;
    int q[4] = {-1, -1, -1, -1};
    int nq = 0;
    for (int i = 0; i < n_in; i++) {
        long long sz = in_sizes[i];
        if (sz == (long long)B_ * S_ * D_)      xi = i;
        else if (sz == P_)                      si = i;
        else if (sz == (long long)B_ * S_)      mi = i;
        else if (sz == (long long)D_ * P_ && nq < 4) q[nq++] = i;
    }
    if (xi < 0 || si < 0 || mi < 0 || nq != 4) {
        xi = 0; q[0] = 1; q[1] = 2; q[2] = 3; q[3] = 4; si = 5; mi = 6;
    }
    const float *w_head, *w_prep, *w_child, *hid;
    if (xi == 0) {
        w_head = (const float*)d_in[q[0]];
        w_prep = (const float*)d_in[q[1]];
        w_child = (const float*)d_in[q[2]];
        hid    = (const float*)d_in[q[3]];
    } else {
        hid    = (const float*)d_in[q[0]];
        w_child = (const float*)d_in[q[1]];
        w_head = (const float*)d_in[q[2]];
        w_prep = (const float*)d_in[q[3]];
    }
    const float* x = (const float*)d_in[xi];
    const float* scorer = (const float*)d_in[si];
    const void* mask = d_in[mi];
    float* out = (float*)d_out;

    __nv_bfloat16 *xb_p, *w1t_p, *h0t_p, *h1t_p, *c0_p, *c1_p;
    cudaGetSymbolAddress((void**)&xb_p,  g_xb);
    cudaGetSymbolAddress((void**)&w1t_p, g_w1t);
    cudaGetSymbolAddress((void**)&h0t_p, g_h0t);
    cudaGetSymbolAddress((void**)&h1t_p, g_h1t);
    cudaGetSymbolAddress((void**)&c0_p,  g_c0);
    cudaGetSymbolAddress((void**)&c1_p,  g_c1);

    cudaFuncSetAttribute(gemm_bf16<1024,0>, cudaFuncAttributeMaxDynamicSharedMemorySize, GSMEM);
    cudaFuncSetAttribute(gemm_bf16<512,1>,  cudaFuncAttributeMaxDynamicSharedMemorySize, GSMEM);
    cudaFuncSetAttribute(gemm_bf16<512,2>,  cudaFuncAttributeMaxDynamicSharedMemorySize, GSMEM);

    mask_probe_kernel<<<1, 256>>>((const unsigned int*)mask);
    convert_x_kernel<<<4096, 256>>>((const float4*)x);
    transpose_all<<<dim3(P_/32, D_/32, 3), 256>>>(w_head, hid);
    bias_kernel<<<dim3(P_/128, B_/4), 512>>>(x, w_prep, w_child);

    gemm_bf16<1024,0><<<dim3(4, NROWS/128), 128, GSMEM>>>(xb_p, w1t_p, scorer, c0_p);
    gemm_bf16<512,1> <<<dim3(4, NROWS/128), 128, GSMEM>>>(c0_p, h0t_p, scorer, c1_p);
    gemm_bf16<512,2> <<<dim3(4, NROWS/128), 128, GSMEM>>>(c1_p, h1t_p, scorer, nullptr);

    softmax_kernel<<<B_, 256>>>(mask, out);
}

// round 14
// speedup vs baseline: 1.7227x; 1.0079x over previous
#include <cuda_runtime.h>
#include <cuda_bf16.h>
#include <cstdint>
#include <cstddef>

// Problem constants
#define B_   256
#define S_   256
#define D_   1024
#define P_   512
#define SH   254
#define NROWS (B_*SH)       // 65024
#define EPS_ 1e-7f

// Scratch (__device__ globals: allocation-free rule)
__device__ float g_bias[B_*P_];
__device__ float g_spart[4*NROWS];                    // per-N-block score partials
__device__ int   g_mask_mode;
__device__ __align__(1024) __nv_bfloat16 g_xb[(size_t)B_*S_*D_];  // x in bf16
__device__ __align__(1024) __nv_bfloat16 g_w1t[(size_t)P_*D_];    // proj_head^T bf16
__device__ __align__(1024) __nv_bfloat16 g_h0t[(size_t)P_*P_];    // hidden0^T bf16
__device__ __align__(1024) __nv_bfloat16 g_h1t[(size_t)P_*P_];    // hidden1^T bf16
__device__ __align__(1024) __nv_bfloat16 g_c0[(size_t)NROWS*P_];  // act after stage 1
__device__ __align__(1024) __nv_bfloat16 g_c1[(size_t)NROWS*P_];  // act after stage 2

__device__ __forceinline__ float fast_tanh(float x) {
    float y; asm("tanh.approx.f32 %0, %1;" : "=f"(y) : "f"(x)); return y;
}
__device__ __forceinline__ uint32_t smem_u32(const void* p) {
    uint32_t a;
    asm("{ .reg .u64 t; cvta.to.shared.u64 t, %1; cvt.u32.u64 %0, t; }" : "=r"(a) : "l"(p));
    return a;
}

// ---------------------------------------------------------------------------
// Fused pre-pass: one launch, role-specialized blocks (all roles independent).
//   blocks [0,128)     : bias, 8 batches/block  (grid was 4 pblk x 32 bblk)
//   blocks [128,640)   : weight transpose -> bf16, 2 (32x32) tiles per block
//   blocks [640,1664)  : x -> bf16 convert, grid-stride over 8.39M uint4
//   block  1664        : mask dtype probe
// Dynamic smem 80KB -> 2 blocks/SM. 512 threads.
// ---------------------------------------------------------------------------
#define PRE_SMEM (20480 * 4)   // 80KB: sP 8K floats | sC 8K | red 4K

__global__ void __launch_bounds__(512) prepass_kernel(
    const float*  __restrict__ x,
    const float*  __restrict__ wp,
    const float*  __restrict__ wc,
    const float*  __restrict__ w_head,
    const float*  __restrict__ hid,
    const unsigned int* __restrict__ mask_w)
{
    extern __shared__ __align__(16) float dsm[];
    const int bx = blockIdx.x;
    const int tid = threadIdx.x;

    if (bx < 128) {
        // ---- bias role: bias[b][p] = prep·wp[:,p] + child·wc[:,p], 8 batches ----
        float* sP  = dsm;            // [8][1024]
        float* sC  = dsm + 8192;     // [8][1024]
        float* red = dsm + 16384;    // [4][8][128]
        const int pblk = bx >> 5, bblk = bx & 31;
        const int b0 = bblk * 8;

        // stage 16 rows (8 prep + 8 child): 4096 float4 by 512 threads
        #pragma unroll
        for (int it = 0; it < 8; it++) {
            int idx  = tid + it * 512;
            int row  = idx >> 8;              // 0..15
            int col4 = idx & 255;
            int bb   = b0 + (row >> 1);
            int which = row & 1;
            const float* src = x + ((size_t)bb * S_ + (S_ - 2) + which) * D_;
            float4 v = *(const float4*)(src + col4 * 4);
            float* dst = (which ? sC : sP) + (row >> 1) * 1024;
            *(float4*)(dst + col4 * 4) = v;
        }
        __syncthreads();

        const int pl = tid & 127;
        const int q  = tid >> 7;              // d-quarter 0..3 (same split as v2)
        const int p  = pblk * 128 + pl;
        const int d0 = q * 256;

        float acc[8];
        #pragma unroll
        for (int j = 0; j < 8; j++) acc[j] = 0.f;
        #pragma unroll 4
        for (int d = d0; d < d0 + 256; d++) {
            float a = wp[(size_t)d * P_ + p];
            float c = wc[(size_t)d * P_ + p];
            #pragma unroll
            for (int j = 0; j < 8; j++)
                acc[j] += sP[j * 1024 + d] * a + sC[j * 1024 + d] * c;
        }
        #pragma unroll
        for (int j = 0; j < 8; j++) red[(q * 8 + j) * 128 + pl] = acc[j];
        __syncthreads();
        if (q == 0) {
            #pragma unroll
            for (int j = 0; j < 8; j++) {
                float v = red[(0 + j) * 128 + pl] + red[(8 + j) * 128 + pl]
                        + red[(16 + j) * 128 + pl] + red[(24 + j) * 128 + pl];
                g_bias[(size_t)(b0 + j) * P_ + p] = v;
            }
        }
    } else if (bx < 640) {
        // ---- transpose role: W[K][512] -> Wt[512][K] bf16; 2 tiles/block ----
        const int tl = tid & 255, tsel = tid >> 8;
        const int t = (bx - 128) * 2 + tsel;      // tile id 0..1023
        int z, u;
        if (t < 512)      { z = 0; u = t; }
        else if (t < 768) { z = 1; u = t - 512; }
        else              { z = 2; u = t - 768; }
        const int K = (z == 0) ? D_ : P_;
        const int pb = u & 15, kb = u >> 4;
        const float* src = (z == 0) ? w_head : (hid + (size_t)(z - 1) * P_ * P_);
        __nv_bfloat16* dst = (z == 0) ? g_w1t : ((z == 1) ? g_h0t : g_h1t);

        float* ts = dsm + tsel * 1056;            // 32x33
        const int k0 = kb * 32, n0 = pb * 32;
        const int tx = tl & 31, ty = tl >> 5;     // 32 x 8
        #pragma unroll
        for (int i = 0; i < 32; i += 8)
            ts[(ty + i) * 33 + tx] = src[(size_t)(k0 + ty + i) * P_ + n0 + tx];
        __syncthreads();
        #pragma unroll
        for (int i = 0; i < 32; i += 8)
            dst[(size_t)(n0 + ty + i) * K + k0 + tx] = __float2bfloat16_rn(ts[tx * 33 + ty + i]);
    } else if (bx < 1664) {
        // ---- convert role: x -> bf16, 16 uint4 per thread (grid-stride) ----
        const size_t n4 = (size_t)B_ * S_ * D_ / 8;
        const float4* x4 = (const float4*)x;
        uint4* dst = (uint4*)g_xb;
        for (size_t i = (size_t)(bx - 640) * 512 + tid; i < n4; i += (size_t)1024 * 512) {
            float4 a = x4[i * 2], b = x4[i * 2 + 1];
            __nv_bfloat162 p0 = __floats2bfloat162_rn(a.x, a.y);
            __nv_bfloat162 p1 = __floats2bfloat162_rn(a.z, a.w);
            __nv_bfloat162 p2 = __floats2bfloat162_rn(b.x, b.y);
            __nv_bfloat162 p3 = __floats2bfloat162_rn(b.z, b.w);
            uint4 o;
            o.x = *(uint32_t*)&p0; o.y = *(uint32_t*)&p1;
            o.z = *(uint32_t*)&p2; o.w = *(uint32_t*)&p3;
            dst[i] = o;
        }
    } else {
        // ---- probe role: classify mask dtype from first 65536 bytes ----
        __shared__ int s01, sf;
        if (tid == 0) { s01 = 1; sf = 1; }
        __syncthreads();
        bool ok01 = true, okf = true;
        #pragma unroll 4
        for (int it = 0; it < 32; it++) {
            unsigned int v = mask_w[tid + it * 512];
            if (v > 1u) ok01 = false;
            if (v != 0u && v != 0x3F800000u) okf = false;
        }
        if (!ok01) atomicAnd(&s01, 0);
        if (!okf)  atomicAnd(&sf, 0);
        __syncthreads();
        if (tid == 0) g_mask_mode = s01 ? 0 : (sf ? 1 : 2);
    }
}

// ---------------------------------------------------------------------------
// bf16 mma.sync GEMM stage. CTA = 128 threads (4 warps, 2M x 2N), tile 128x128,
// warp tile 64x64, BK=64 bf16 (128B rows), 3-stage cp.async, 96KB -> 2 CTAs/SM.
// mma m16n8k16, fp32 accumulate.
// EPI: 0 = +bias,tanh -> bf16 Cout ; 1 = tanh -> bf16 Cout ; 2 = tanh + scorer partial
// ---------------------------------------------------------------------------
#define GSMEM 98304

template<int K, int EPI>
__global__ void __launch_bounds__(128, 2) gemm_bf16(
    const __nv_bfloat16* __restrict__ A,
    const __nv_bfloat16* __restrict__ BT,
    const float* __restrict__ scorer,
    __nv_bfloat16* __restrict__ Cout)
{
    constexpr int T = K / 64;
    extern __shared__ __align__(1024) char smem[];
    const uint32_t sb = smem_u32(smem);
    const int tid = threadIdx.x, lane = tid & 31, wid = tid >> 5;
    const int wm = wid >> 1, wn = wid & 1;
    const int N0 = blockIdx.x * 128, R0 = blockIdx.y * 128;

    const int r0 = tid >> 3, cc = tid & 7;
    const uint32_t sA0 = (uint32_t)(r0 * 128 + ((cc ^ (r0 & 7)) << 4));
    uint32_t aoff[8];   // byte offsets
    #pragma unroll
    for (int i = 0; i < 8; i++) {
        int r = R0 + r0 + i * 16;
        if (EPI == 0) {
            int b = r / SH; int s2 = r - b * SH;
            aoff[i] = (uint32_t)(((b * S_ + s2) * D_ + cc * 8) * 2);
        } else {
            aoff[i] = (uint32_t)((r * K + cc * 8) * 2);
        }
    }
    const uint32_t boff0 = (uint32_t)(((N0 + r0) * K + cc * 8) * 2);
    const char* Ab = (const char*)A;
    const char* Bb = (const char*)BT;

    auto fill = [&](int slot, int kt) {
        uint32_t base = sb + slot * 32768;
        uint32_t koff = (uint32_t)kt * 128;   // 64 bf16 = 128 bytes
        #pragma unroll
        for (int i = 0; i < 8; i++)
            asm volatile("cp.async.cg.shared.global [%0], [%1], 16;"
                :: "r"(base + sA0 + i * 2048), "l"(Ab + aoff[i] + koff) : "memory");
        #pragma unroll
        for (int i = 0; i < 8; i++)
            asm volatile("cp.async.cg.shared.global [%0], [%1], 16;"
                :: "r"(base + 16384 + sA0 + i * 2048),
                   "l"(Bb + boff0 + (uint32_t)i * (16u * K * 2u) + koff) : "memory");
        asm volatile("cp.async.commit_group;" ::: "memory");
    };

    float acc[4][8][4];
    #pragma unroll
    for (int a = 0; a < 4; a++)
        #pragma unroll
        for (int b = 0; b < 8; b++)
            #pragma unroll
            for (int c = 0; c < 4; c++) acc[a][b][c] = 0.f;

    fill(0, 0);
    fill(1, 1);
    fill(2, 2);

    const int lrow = lane & 15;
    const int lhalf = lane >> 4;
    const int lswz = lrow & 7;

    for (int t = 0; t < T; t++) {
        int rem = T - 1 - t;
        if (rem >= 2)      asm volatile("cp.async.wait_group 2;" ::: "memory");
        else if (rem == 1) asm volatile("cp.async.wait_group 1;" ::: "memory");
        else               asm volatile("cp.async.wait_group 0;" ::: "memory");
        __syncthreads();

        const int slot = t % 3;
        const uint32_t ab = sb + slot * 32768;
        const uint32_t bbs = ab + 16384;
        #pragma unroll
        for (int kk = 0; kk < 4; kk++) {
            const uint32_t coff = (uint32_t)(((kk * 2 + lhalf) ^ lswz) << 4);
            uint32_t ar[4][4], br[4][4];
            #pragma unroll
            for (int mi = 0; mi < 4; mi++) {
                uint32_t addr = ab + (uint32_t)((wm * 64 + mi * 16 + lrow) * 128) + coff;
                asm volatile("ldmatrix.sync.aligned.m8n8.x4.shared.b16 {%0,%1,%2,%3}, [%4];"
                    : "=r"(ar[mi][0]), "=r"(ar[mi][1]), "=r"(ar[mi][2]), "=r"(ar[mi][3])
                    : "r"(addr));
            }
            #pragma unroll
            for (int np = 0; np < 4; np++) {
                uint32_t addr = bbs + (uint32_t)((wn * 64 + np * 16 + lrow) * 128) + coff;
                asm volatile("ldmatrix.sync.aligned.m8n8.x4.shared.b16 {%0,%1,%2,%3}, [%4];"
                    : "=r"(br[np][0]), "=r"(br[np][1]), "=r"(br[np][2]), "=r"(br[np][3])
                    : "r"(addr));
            }
            #pragma unroll
            for (int mi = 0; mi < 4; mi++)
                #pragma unroll
                for (int nj = 0; nj < 8; nj++) {
                    uint32_t b0 = br[nj >> 1][nj & 1];
                    uint32_t b1 = br[nj >> 1][(nj & 1) + 2];
                    asm volatile(
                        "mma.sync.aligned.m16n8k16.row.col.f32.bf16.bf16.f32 "
                        "{%0,%1,%2,%3}, {%4,%5,%6,%7}, {%8,%9}, {%0,%1,%2,%3};"
                        : "+f"(acc[mi][nj][0]), "+f"(acc[mi][nj][1]),
                          "+f"(acc[mi][nj][2]), "+f"(acc[mi][nj][3])
                        : "r"(ar[mi][0]), "r"(ar[mi][1]), "r"(ar[mi][2]), "r"(ar[mi][3]),
                          "r"(b0), "r"(b1));
                }
        }
        __syncthreads();
        if (t + 3 < T) fill(slot, t + 3);
    }

    // ---- epilogue ----
    const int r4 = lane >> 2, l2 = (lane & 3) * 2;
    if (EPI < 2) {
        #pragma unroll
        for (int mi = 0; mi < 4; mi++)
            #pragma unroll
            for (int h = 0; h < 2; h++) {
                int m = R0 + wm * 64 + mi * 16 + r4 + h * 8;
                const float* brow_ = g_bias + (size_t)(m / SH) * P_;
                #pragma unroll
                for (int nj = 0; nj < 8; nj++) {
                    int n = N0 + wn * 64 + nj * 8 + l2;
                    float v0 = acc[mi][nj][h * 2 + 0];
                    float v1 = acc[mi][nj][h * 2 + 1];
                    if (EPI == 0) {
                        float2 bv = *(const float2*)(brow_ + n);
                        v0 += bv.x; v1 += bv.y;
                    }
                    __nv_bfloat162 o = __floats2bfloat162_rn(fast_tanh(v0), fast_tanh(v1));
                    *(uint32_t*)(Cout + (size_t)m * P_ + n) = *(uint32_t*)&o;
                }
            }
    } else {
        __syncthreads();                    // smem reuse for reduction
        float* red = (float*)smem;          // [2][128]
        #pragma unroll
        for (int mi = 0; mi < 4; mi++)
            #pragma unroll
            for (int h = 0; h < 2; h++) {
                float sum = 0.f;
                #pragma unroll
                for (int nj = 0; nj < 8; nj++) {
                    int n = N0 + wn * 64 + nj * 8 + l2;
                    float v0 = fast_tanh(acc[mi][nj][h * 2 + 0]);
                    float v1 = fast_tanh(acc[mi][nj][h * 2 + 1]);
                    sum += v0 * __ldg(scorer + n) + v1 * __ldg(scorer + n + 1);
                }
                sum += __shfl_xor_sync(0xffffffffu, sum, 1);
                sum += __shfl_xor_sync(0xffffffffu, sum, 2);
                if ((lane & 3) == 0)
                    red[wn * 128 + wm * 64 + mi * 16 + r4 + h * 8] = sum;
            }
        __syncthreads();
        float tot = red[tid] + red[128 + tid];
        g_spart[(size_t)blockIdx.x * NROWS + R0 + tid] = tot;
    }
}

// ---------------------------------------------------------------------------
// masked softmax over s per batch; sums the 4 N-block score partials.
// ---------------------------------------------------------------------------
__global__ void __launch_bounds__(256) softmax_kernel(
    const void* __restrict__ mask_raw, float* __restrict__ out)
{
    __shared__ float red[256];
    const int b = blockIdx.x;
    const int s = threadIdx.x;
    const int mode = g_mask_mode;
    float e = 0.f;
    if (s < SH) {
        bool m;
        int idx = b * S_ + s;
        if (mode == 0)      m = ((const int*)mask_raw)[idx] != 0;
        else if (mode == 1) m = ((const float*)mask_raw)[idx] != 0.f;
        else                m = ((const unsigned char*)mask_raw)[idx] != 0;
        int r = b * SH + s;
        float sc = g_spart[r] + g_spart[NROWS + r] + g_spart[2 * NROWS + r] + g_spart[3 * NROWS + r];
        e = m ? expf(sc) : 0.f;
    }
    red[s] = e;
    __syncthreads();
    #pragma unroll
    for (int o = 128; o > 0; o >>= 1) {
        if (s < o) red[s] += red[s + o];
        __syncthreads();
    }
    float inv = 1.f / (red[0] + EPS_);
    if (s < SH) out[b * SH + s] = e * inv;
}

// ---------------------------------------------------------------------------
extern "C" void kernel_launch(void* const* d_in, const int* in_sizes, int n_in,
                              void* d_out, int out_size)
{
    // Resolve inputs by element count (robust to metadata ordering).
    int xi = -1, si = -1, mi = -1;
    int q[4] = {-1, -1, -1, -1};
    int nq = 0;
    for (int i = 0; i < n_in; i++) {
        long long sz = in_sizes[i];
        if (sz == (long long)B_ * S_ * D_)      xi = i;
        else if (sz == P_)                      si = i;
        else if (sz == (long long)B_ * S_)      mi = i;
        else if (sz == (long long)D_ * P_ && nq < 4) q[nq++] = i;
    }
    if (xi < 0 || si < 0 || mi < 0 || nq != 4) {
        xi = 0; q[0] = 1; q[1] = 2; q[2] = 3; q[3] = 4; si = 5; mi = 6;
    }
    const float *w_head, *w_prep, *w_child, *hid;
    if (xi == 0) {
        w_head = (const float*)d_in[q[0]];
        w_prep = (const float*)d_in[q[1]];
        w_child = (const float*)d_in[q[2]];
        hid    = (const float*)d_in[q[3]];
    } else {
        hid    = (const float*)d_in[q[0]];
        w_child = (const float*)d_in[q[1]];
        w_head = (const float*)d_in[q[2]];
        w_prep = (const float*)d_in[q[3]];
    }
    const float* x = (const float*)d_in[xi];
    const float* scorer = (const float*)d_in[si];
    const void* mask = d_in[mi];
    float* out = (float*)d_out;

    __nv_bfloat16 *xb_p, *w1t_p, *h0t_p, *h1t_p, *c0_p, *c1_p;
    cudaGetSymbolAddress((void**)&xb_p,  g_xb);
    cudaGetSymbolAddress((void**)&w1t_p, g_w1t);
    cudaGetSymbolAddress((void**)&h0t_p, g_h0t);
    cudaGetSymbolAddress((void**)&h1t_p, g_h1t);
    cudaGetSymbolAddress((void**)&c0_p,  g_c0);
    cudaGetSymbolAddress((void**)&c1_p,  g_c1);

    cudaFuncSetAttribute(prepass_kernel,    cudaFuncAttributeMaxDynamicSharedMemorySize, PRE_SMEM);
    cudaFuncSetAttribute(gemm_bf16<1024,0>, cudaFuncAttributeMaxDynamicSharedMemorySize, GSMEM);
    cudaFuncSetAttribute(gemm_bf16<512,1>,  cudaFuncAttributeMaxDynamicSharedMemorySize, GSMEM);
    cudaFuncSetAttribute(gemm_bf16<512,2>,  cudaFuncAttributeMaxDynamicSharedMemorySize, GSMEM);

    prepass_kernel<<<1665, 512, PRE_SMEM>>>(x, w_prep, w_child, w_head, hid,
                                            (const unsigned int*)mask);

    gemm_bf16<1024,0><<<dim3(4, NROWS/128), 128, GSMEM>>>(xb_p, w1t_p, scorer, c0_p);
    gemm_bf16<512,1> <<<dim3(4, NROWS/128), 128, GSMEM>>>(c0_p, h0t_p, scorer, c1_p);
    gemm_bf16<512,2> <<<dim3(4, NROWS/128), 128, GSMEM>>>(c1_p, h1t_p, scorer, nullptr);

    softmax_kernel<<<B_, 256>>>(mask, out);
}